// round 12
// baseline (speedup 1.0000x reference)
#include <cuda_runtime.h>
#include <cstdint>

#define Nn 100000
#define Ee 1600000
#define Dd 128
#define Ll 3
#define Gg 5000
#define GB 782

// ================= scratch =================
__device__ float g_x[Nn * Dd];
__device__ float g_y[Nn * Dd];
// agg bf16 hi/lo GEMM-tile images: [img][tile][kc][16KB swizzled chunk]
__device__ unsigned short g_Abf[2][GB * 2 * 8192];
__device__ unsigned short g_Wbf[6][2][Dd * Dd];
__device__ float g_W1T[Dd * Dd];
__device__ int   g_deg[Nn];
__device__ float g_invdeg[Nn];
__device__ int   g_rowoff[Nn + 1];
__device__ int   g_cursor[Nn];
__device__ int   g_csr[Ee];
__device__ int   g_part[256];
__device__ int   g_centers[Gg];

#define SCAN_B 256
#define SCAN_T 512
#define CHUNK ((Nn + SCAN_B - 1) / SCAN_B)

__device__ __forceinline__ uint32_t sw128(uint32_t o) { return o ^ ((o >> 3) & 0x70u); }
__device__ __forceinline__ void cp_async16(uint32_t smem_dst, const void* gsrc) {
    asm volatile("cp.async.cg.shared.global [%0], [%1], 16;"
                 :: "r"(smem_dst), "l"(gsrc));
}
__device__ __forceinline__ uint32_t smem_to_u32(const void* p) {
    uint32_t a;
    asm("{ .reg .u64 t; cvta.to.shared.u64 t, %1; cvt.u32.u64 %0, t; }"
        : "=r"(a) : "l"(p));
    return a;
}

// ================= fused setup =================
#define ZB 391
#define EB 12500
#define WC 384
#define T1 64
#define CB 20
__global__ void k_setup(const int* __restrict__ z, const float* __restrict__ zt,
                        const float* __restrict__ Wl, const float* __restrict__ Wr,
                        const float* __restrict__ W1, const int* __restrict__ batch) {
    int b = blockIdx.x, t = threadIdx.x;
    if (b < ZB) {
        int i = b * 256 + t;
        if (i < Nn) g_deg[i] = 0;
    } else if (b < ZB + EB) {
        int i = (b - ZB) * 256 + t;
        int n = i >> 5, q = i & 31;
        int zz = z[n];
        *(float4*)(g_x + n * Dd + q * 4) = *(const float4*)(zt + zz * Dd + q * 4);
    } else if (b < ZB + EB + WC) {
        int i = (b - ZB - EB) * 256 + t;   // 6*16384 (m, n, k)
        int m = i >> 14;
        int n = (i >> 7) & 127;
        int k = i & 127;
        const float* src = (m & 1) ? (Wr + (m >> 1) * Dd * Dd) : (Wl + (m >> 1) * Dd * Dd);
        float w = src[n * Dd + k];
        uint32_t u = __float_as_uint(w);
        uint32_t hb = (u + 0x7fffu + ((u >> 16) & 1u)) >> 16;
        float hf = __uint_as_float(hb << 16);
        float l = w - hf;
        uint32_t ul = __float_as_uint(l);
        uint32_t lb = (ul + 0x7fffu + ((ul >> 16) & 1u)) >> 16;
        uint32_t off = (uint32_t)(k >> 6) * 16384u
                     + sw128((uint32_t)n * 128u + (uint32_t)(k & 63) * 2u);
        *(unsigned short*)((char*)g_Wbf[m][0] + off) = (unsigned short)hb;
        *(unsigned short*)((char*)g_Wbf[m][1] + off) = (unsigned short)lb;
    } else if (b < ZB + EB + WC + T1) {
        int i = (b - ZB - EB - WC) * 256 + t;
        int k = i >> 7, j = i & 127;
        g_W1T[i] = W1[j * Dd + k];
    } else {
        int g = (b - ZB - EB - WC - T1) * 256 + t;
        if (g < Gg) {
            int lo = 0, hi = Nn;
            while (lo < hi) {
                int mid = (lo + hi) >> 1;
                if (batch[mid] < g) lo = mid + 1; else hi = mid;
            }
            g_centers[g] = lo;
        }
    }
}

// ================= CSR build =================
__global__ void k_deg(const int* __restrict__ dst) {
    int e = blockIdx.x * blockDim.x + threadIdx.x;
    if (e < Ee) atomicAdd(&g_deg[dst[e]], 1);
}
__global__ void k_scan1() {
    __shared__ int sh[SCAN_T];
    int b = blockIdx.x, t = threadIdx.x;
    int i = b * CHUNK + t;
    int v = (t < CHUNK && i < Nn) ? g_deg[i] : 0;
    sh[t] = v;
    __syncthreads();
    for (int off = 1; off < SCAN_T; off <<= 1) {
        int y = (t >= off) ? sh[t - off] : 0;
        __syncthreads();
        sh[t] += y;
        __syncthreads();
    }
    if (t < CHUNK && i < Nn) g_rowoff[i] = sh[t] - v;
    if (t == SCAN_T - 1) g_part[b] = sh[SCAN_T - 1];
}
__global__ void k_scan2() {
    __shared__ int sh[SCAN_B];
    int t = threadIdx.x;
    int v = g_part[t];
    sh[t] = v;
    __syncthreads();
    for (int off = 1; off < SCAN_B; off <<= 1) {
        int y = (t >= off) ? sh[t - off] : 0;
        __syncthreads();
        sh[t] += y;
        __syncthreads();
    }
    g_part[t] = sh[t] - v;
}
__global__ void k_scan3() {
    int b = blockIdx.x, t = threadIdx.x;
    int i = b * CHUNK + t;
    if (t < CHUNK && i < Nn) {
        int v = g_rowoff[i] + g_part[b];
        g_rowoff[i] = v;
        g_cursor[i] = v;
        int d = g_deg[i];
        g_invdeg[i] = 1.0f / (float)(d > 0 ? d : 1);
    }
    if (b == 0 && t == 0) g_rowoff[Nn] = Ee;
}
__global__ void k_csr(const int* __restrict__ src, const int* __restrict__ dst) {
    int e = blockIdx.x * blockDim.x + threadIdx.x;
    if (e < Ee) {
        int d = dst[e];
        int pos = atomicAdd(&g_cursor[d], 1);
        g_csr[pos] = src[e];
    }
}

// ================= aggregation: gather + direct bf16 hi/lo image write ==========
__global__ void __launch_bounds__(256) k_agg(int xsel) {
    const float* __restrict__ x = xsel ? g_y : g_x;
    int w = (blockIdx.x * blockDim.x + threadIdx.x) >> 5;
    if (w >= Nn) return;
    int lane = threadIdx.x & 31;
    int beg = g_rowoff[w], end = g_rowoff[w + 1];
    float4 a0 = make_float4(0.f, 0.f, 0.f, 0.f);
    float4 a1 = make_float4(0.f, 0.f, 0.f, 0.f);
    float4 a2 = make_float4(0.f, 0.f, 0.f, 0.f);
    float4 a3 = make_float4(0.f, 0.f, 0.f, 0.f);
    int e = beg;
    for (; e + 4 <= end; e += 4) {
        int s0 = g_csr[e], s1 = g_csr[e + 1], s2 = g_csr[e + 2], s3 = g_csr[e + 3];
        float4 v0 = *(const float4*)(x + s0 * Dd + lane * 4);
        float4 v1 = *(const float4*)(x + s1 * Dd + lane * 4);
        float4 v2 = *(const float4*)(x + s2 * Dd + lane * 4);
        float4 v3 = *(const float4*)(x + s3 * Dd + lane * 4);
        a0.x += v0.x; a0.y += v0.y; a0.z += v0.z; a0.w += v0.w;
        a1.x += v1.x; a1.y += v1.y; a1.z += v1.z; a1.w += v1.w;
        a2.x += v2.x; a2.y += v2.y; a2.z += v2.z; a2.w += v2.w;
        a3.x += v3.x; a3.y += v3.y; a3.z += v3.z; a3.w += v3.w;
    }
    for (; e < end; e++) {
        int s0 = g_csr[e];
        float4 v0 = *(const float4*)(x + s0 * Dd + lane * 4);
        a0.x += v0.x; a0.y += v0.y; a0.z += v0.z; a0.w += v0.w;
    }
    float sc = g_invdeg[w];
    float4 r;
    r.x = (a0.x + a1.x + a2.x + a3.x) * sc;
    r.y = (a0.y + a1.y + a2.y + a3.y) * sc;
    r.z = (a0.z + a1.z + a2.z + a3.z) * sc;
    r.w = (a0.w + a1.w + a2.w + a3.w) * sc;
    // ---- bf16 hi/lo split (identical math to the GEMM's converter) ----
    uint32_t h0, h1, l0, l1;
    asm("cvt.rn.bf16x2.f32 %0, %1, %2;" : "=r"(h0) : "f"(r.y), "f"(r.x));
    asm("cvt.rn.bf16x2.f32 %0, %1, %2;" : "=r"(h1) : "f"(r.w), "f"(r.z));
    float e0 = r.x - __uint_as_float(h0 << 16);
    float e1 = r.y - __uint_as_float(h0 & 0xffff0000u);
    float e2 = r.z - __uint_as_float(h1 << 16);
    float e3 = r.w - __uint_as_float(h1 & 0xffff0000u);
    asm("cvt.rn.bf16x2.f32 %0, %1, %2;" : "=r"(l0) : "f"(e1), "f"(e0));
    asm("cvt.rn.bf16x2.f32 %0, %1, %2;" : "=r"(l1) : "f"(e3), "f"(e2));
    int tile = w >> 7, rr = w & 127;
    int k0 = lane * 4;
    uint32_t off = sw128((uint32_t)(rr * 128 + (k0 & 63) * 2));
    size_t base = ((size_t)tile * 2 + (size_t)(k0 >> 6)) * 16384 + off;
    *(uint2*)((char*)g_Abf[0] + base) = make_uint2(h0, h1);
    *(uint2*)((char*)g_Abf[1] + base) = make_uint2(l0, l1);
}

// ================= mma.sync bf16-split GEMM =================
// aimg=1: A from precomputed g_Abf images (cp.async); aimg=0: convert f32 S.
#define HG_SMEM 65536
extern __shared__ char s_hg[];

__device__ __forceinline__ void ldmx4(uint32_t addr, uint32_t f[4]) {
    asm volatile("ldmatrix.sync.aligned.m8n8.x4.shared.b16 {%0,%1,%2,%3}, [%4];"
                 : "=r"(f[0]), "=r"(f[1]), "=r"(f[2]), "=r"(f[3]) : "r"(addr));
}
__device__ __forceinline__ void mma16816(float d[4], const uint32_t a[4],
                                         uint32_t b0, uint32_t b1) {
    asm volatile(
        "mma.sync.aligned.m16n8k16.row.col.f32.bf16.bf16.f32 "
        "{%0,%1,%2,%3}, {%4,%5,%6,%7}, {%8,%9}, {%0,%1,%2,%3};"
        : "+f"(d[0]), "+f"(d[1]), "+f"(d[2]), "+f"(d[3])
        : "r"(a[0]), "r"(a[1]), "r"(a[2]), "r"(a[3]), "r"(b0), "r"(b1));
}

__global__ void __launch_bounds__(256, 3) k_hgemm(int s1sel, int m1, int osel,
                                                  const float* __restrict__ bias,
                                                  int relu, int rmw, int aimg) {
    const float* bufs[2] = {g_x, g_y};
    float* obufs[2] = {g_x, g_y};
    const float* __restrict__ S = bufs[s1sel];
    float* __restrict__ O = obufs[osel];

    uint32_t sb = smem_to_u32(s_hg);
    uint32_t sAhi = sb, sAlo = sb + 16384u, sWhi = sb + 32768u, sWlo = sb + 49152u;
    int tid = threadIdx.x, lane = tid & 31, wid = tid >> 5;
    int wm = wid & 3, wn = wid >> 2;
    int rowBase = blockIdx.x * 128;

    float d[2][8][4];
#pragma unroll
    for (int mt = 0; mt < 2; mt++)
#pragma unroll
        for (int i = 0; i < 8; i++)
#pragma unroll
            for (int j = 0; j < 4; j++) d[mt][i][j] = 0.f;

    int fr = (lane & 7) + ((lane >> 3) & 1) * 8;
    int fk = (lane >> 4) * 8;

    for (int kc = 0; kc < 2; kc++) {
        __syncthreads();
        // ---- async W-image copy ----
        {
            const char* whp = (const char*)g_Wbf[m1][0] + kc * 16384;
            const char* wlp = (const char*)g_Wbf[m1][1] + kc * 16384;
#pragma unroll
            for (int i = tid; i < 1024; i += 256) {
                cp_async16(sWhi + (uint32_t)i * 16u, whp + i * 16);
                cp_async16(sWlo + (uint32_t)i * 16u, wlp + i * 16);
            }
        }
        if (aimg) {
            // ---- A images precomputed: pure cp.async ----
            size_t cbase = ((size_t)blockIdx.x * 2 + (size_t)kc) * 16384;
            const char* ahp = (const char*)g_Abf[0] + cbase;
            const char* alp = (const char*)g_Abf[1] + cbase;
#pragma unroll
            for (int i = tid; i < 1024; i += 256) {
                cp_async16(sAhi + (uint32_t)i * 16u, ahp + i * 16);
                cp_async16(sAlo + (uint32_t)i * 16u, alp + i * 16);
            }
            asm volatile("cp.async.commit_group;" ::: "memory");
        } else {
            asm volatile("cp.async.commit_group;" ::: "memory");
            // ---- load + convert A chunk: 128 rows x 64 k ----
            int row = tid >> 1, half = tid & 1;
            int grow = rowBase + row;
            const float4* p = (const float4*)(S + (size_t)grow * Dd + kc * 64 + half * 32);
            bool valid = grow < Nn;
#pragma unroll
            for (int j = 0; j < 4; j++) {
                float4 v0 = valid ? p[2 * j] : make_float4(0.f, 0.f, 0.f, 0.f);
                float4 v1 = valid ? p[2 * j + 1] : make_float4(0.f, 0.f, 0.f, 0.f);
                uint32_t h0, h1, h2, h3, l0, l1, l2, l3;
                asm("cvt.rn.bf16x2.f32 %0, %1, %2;" : "=r"(h0) : "f"(v0.y), "f"(v0.x));
                asm("cvt.rn.bf16x2.f32 %0, %1, %2;" : "=r"(h1) : "f"(v0.w), "f"(v0.z));
                asm("cvt.rn.bf16x2.f32 %0, %1, %2;" : "=r"(h2) : "f"(v1.y), "f"(v1.x));
                asm("cvt.rn.bf16x2.f32 %0, %1, %2;" : "=r"(h3) : "f"(v1.w), "f"(v1.z));
                float r0x = v0.x - __uint_as_float(h0 << 16);
                float r0y = v0.y - __uint_as_float(h0 & 0xffff0000u);
                float r0z = v0.z - __uint_as_float(h1 << 16);
                float r0w = v0.w - __uint_as_float(h1 & 0xffff0000u);
                float r1x = v1.x - __uint_as_float(h2 << 16);
                float r1y = v1.y - __uint_as_float(h2 & 0xffff0000u);
                float r1z = v1.z - __uint_as_float(h3 << 16);
                float r1w = v1.w - __uint_as_float(h3 & 0xffff0000u);
                asm("cvt.rn.bf16x2.f32 %0, %1, %2;" : "=r"(l0) : "f"(r0y), "f"(r0x));
                asm("cvt.rn.bf16x2.f32 %0, %1, %2;" : "=r"(l1) : "f"(r0w), "f"(r0z));
                asm("cvt.rn.bf16x2.f32 %0, %1, %2;" : "=r"(l2) : "f"(r1y), "f"(r1x));
                asm("cvt.rn.bf16x2.f32 %0, %1, %2;" : "=r"(l3) : "f"(r1w), "f"(r1z));
                uint32_t off = sw128((uint32_t)(row * 128 + (half * 32 + j * 8) * 2));
                *(uint4*)(s_hg + off) = make_uint4(h0, h1, h2, h3);
                *(uint4*)(s_hg + 16384 + off) = make_uint4(l0, l1, l2, l3);
            }
        }
        asm volatile("cp.async.wait_group 0;" ::: "memory");
        __syncthreads();
        // ---- 4 k-steps of 16 ----
#pragma unroll
        for (int ks = 0; ks < 4; ks++) {
            uint32_t aHi[2][4], aLo[2][4];
#pragma unroll
            for (int mt = 0; mt < 2; mt++) {
                uint32_t off = sw128((uint32_t)((wm * 32 + mt * 16 + fr) * 128
                                                + (ks * 16 + fk) * 2));
                ldmx4(sAhi + off, aHi[mt]);
                ldmx4(sAlo + off, aLo[mt]);
            }
#pragma unroll
            for (int nc = 0; nc < 4; nc++) {
                uint32_t off = sw128((uint32_t)((wn * 64 + nc * 16 + fr) * 128
                                                + (ks * 16 + fk) * 2));
                uint32_t bH[4], bL[4];
                ldmx4(sWhi + off, bH);
                ldmx4(sWlo + off, bL);
#pragma unroll
                for (int mt = 0; mt < 2; mt++) {
                    mma16816(d[mt][nc * 2 + 0], aHi[mt], bH[0], bH[2]);
                    mma16816(d[mt][nc * 2 + 1], aHi[mt], bH[1], bH[3]);
                    mma16816(d[mt][nc * 2 + 0], aHi[mt], bL[0], bL[2]);
                    mma16816(d[mt][nc * 2 + 1], aHi[mt], bL[1], bL[3]);
                    mma16816(d[mt][nc * 2 + 0], aLo[mt], bH[0], bH[2]);
                    mma16816(d[mt][nc * 2 + 1], aLo[mt], bH[1], bH[3]);
                }
            }
        }
    }

    // ---- epilogue ----
#pragma unroll
    for (int mt = 0; mt < 2; mt++) {
        int row0 = rowBase + wm * 32 + mt * 16 + (lane >> 2);
#pragma unroll
        for (int i = 0; i < 8; i++) {
            int col = wn * 64 + i * 8 + (lane & 3) * 2;
            float2 bv = bias ? *(const float2*)(bias + col) : make_float2(0.f, 0.f);
#pragma unroll
            for (int h = 0; h < 2; h++) {
                int row = row0 + h * 8;
                if (row < Nn) {
                    float2 o;
                    o.x = d[mt][i][2 * h + 0] + bv.x;
                    o.y = d[mt][i][2 * h + 1] + bv.y;
                    float* op = O + (size_t)row * Dd + col;
                    if (rmw) {
                        float2 pv = *(const float2*)op;
                        o.x += pv.x; o.y += pv.y;
                    }
                    if (relu) {
                        o.x = fmaxf(o.x, 0.f);
                        o.y = fmaxf(o.y, 0.f);
                    }
                    *(float2*)op = o;
                }
            }
        }
    }
}

// ================= readout =================
__global__ void __launch_bounds__(128) k_readout(const float* __restrict__ b1,
                                                 const float* __restrict__ W2,
                                                 const float* __restrict__ b2,
                                                 float* __restrict__ out) {
    __shared__ float h[128];
    __shared__ float red[4];
    int g = blockIdx.x, j = threadIdx.x;
    int c = g_centers[g];
    h[j] = g_y[c * Dd + j] * g_y[(c + 1) * Dd + j];
    __syncthreads();
    float t = b1[j];
    const float* __restrict__ w1t = g_W1T + j;
#pragma unroll 8
    for (int k = 0; k < 128; k++) t += h[k] * w1t[k * 128];
    t = fmaxf(t, 0.f) * W2[j];
    for (int off = 16; off; off >>= 1) t += __shfl_down_sync(0xffffffffu, t, off);
    if ((j & 31) == 0) red[j >> 5] = t;
    __syncthreads();
    if (j == 0) out[g] = red[0] + red[1] + red[2] + red[3] + b2[0];
}

// ================= launch: R10 fork-join schedule =================
extern "C" void kernel_launch(void* const* d_in, const int* in_sizes, int n_in,
                              void* d_out, int out_size) {
    const int*   z     = (const int*)d_in[0];
    const int*   ei    = (const int*)d_in[1];
    const int*   batch = (const int*)d_in[2];
    const float* zt    = (const float*)d_in[3];
    const float* Wl    = (const float*)d_in[4];
    const float* bl    = (const float*)d_in[5];
    const float* Wr    = (const float*)d_in[6];
    const float* W1    = (const float*)d_in[7];
    const float* b1    = (const float*)d_in[8];
    const float* W2    = (const float*)d_in[9];
    const float* b2    = (const float*)d_in[10];
    float* out = (float*)d_out;

    const int* esrc = ei;
    const int* edst = ei + Ee;

    static cudaStream_t sB = nullptr;
    static cudaEvent_t evF[Ll], evJ[Ll];
    if (!sB) {
        cudaStreamCreateWithFlags(&sB, cudaStreamNonBlocking);
        for (int i = 0; i < Ll; i++) {
            cudaEventCreateWithFlags(&evF[i], cudaEventDisableTiming);
            cudaEventCreateWithFlags(&evJ[i], cudaEventDisableTiming);
        }
    }
    cudaStream_t s0 = (cudaStream_t)0;

    cudaFuncSetAttribute(k_hgemm, cudaFuncAttributeMaxDynamicSharedMemorySize, HG_SMEM);
    cudaFuncSetAttribute(k_hgemm, cudaFuncAttributePreferredSharedMemoryCarveout, 100);

    int aggGrid = (Nn * 32 + 255) / 256;
    int eGrid = (Ee + 255) / 256;

    // buffers: 0=g_x, 1=g_y; weights: 2l=Wl_l, 2l+1=Wr_l
    k_setup<<<ZB + EB + WC + T1 + CB, 256, 0, s0>>>(z, zt, Wl, Wr, W1, batch);  // #1
    cudaEventRecord(evF[0], s0);
    k_deg<<<eGrid, 256, 0, s0>>>(edst);                                          // #2
    k_scan1<<<SCAN_B, SCAN_T, 0, s0>>>();                                        // #3
    cudaStreamWaitEvent(sB, evF[0], 0);
    k_hgemm<<<GB, 256, HG_SMEM, sB>>>(0, 1, 1, nullptr, 0, 0, 0);                // #4 <- profiled: g_y = x@Wr0
    k_scan2<<<1, SCAN_B, 0, s0>>>();                                             // #5
    k_scan3<<<SCAN_B, SCAN_T, 0, s0>>>();                                        // #6
    k_csr<<<eGrid, 256, 0, s0>>>(esrc, edst);                                    // #7
    k_agg<<<aggGrid, 256, 0, s0>>>(0);                                           // #8
    cudaEventRecord(evJ[0], sB);
    cudaStreamWaitEvent(s0, evJ[0], 0);
    k_hgemm<<<GB, 256, HG_SMEM, s0>>>(0, 0, 1, bl, 1, 1, 1);                     // #9: g_y += img@Wl0 +b, relu

    for (int l = 1; l < Ll; l++) {
        int xs = (l == 1) ? 1 : 0;
        int os = (l == 1) ? 0 : 1;
        cudaEventRecord(evF[l], s0);
        cudaStreamWaitEvent(sB, evF[l], 0);
        k_hgemm<<<GB, 256, HG_SMEM, sB>>>(xs, 2 * l + 1, os, nullptr, 0, 0, 0);  // Wr (convert mode, hidden)
        k_agg<<<aggGrid, 256, 0, s0>>>(xs);                                      // agg -> bf16 images
        cudaEventRecord(evJ[l], sB);
        cudaStreamWaitEvent(s0, evJ[l], 0);
        k_hgemm<<<GB, 256, HG_SMEM, s0>>>(0, 2 * l, os, bl + l * Dd,
                                          (l < Ll - 1) ? 1 : 0, 1, 1);           // Wl (image mode)
    }

    k_readout<<<Gg, 128, 0, s0>>>(b1, W2, b2, out);
}

// round 14
// speedup vs baseline: 1.4224x; 1.4224x over previous
#include <cuda_runtime.h>
#include <cstdint>

#define Nn 100000
#define Ee 1600000
#define Dd 128
#define Ll 3
#define Gg 5000
#define GB 782

// ================= scratch =================
__device__ float g_x[Nn * Dd];
__device__ float g_y[Nn * Dd];
// agg bf16 hi/lo GEMM-tile images: [img][tile][kc][16KB swizzled chunk]
__device__ unsigned short g_Abf[2][GB * 2 * 8192];
__device__ unsigned short g_Wbf[6][2][Dd * Dd];
__device__ float g_W1T[Dd * Dd];
__device__ int   g_deg[Nn];
__device__ float g_invdeg[Nn];
__device__ int   g_rowoff[Nn + 1];
__device__ int   g_cursor[Nn];
__device__ int   g_csr[Ee];
__device__ int   g_part[256];
__device__ int   g_centers[Gg];

#define SCAN_B 256
#define SCAN_T 512
#define CHUNK ((Nn + SCAN_B - 1) / SCAN_B)

__device__ __forceinline__ uint32_t sw128(uint32_t o) { return o ^ ((o >> 3) & 0x70u); }
__device__ __forceinline__ void cp_async16(uint32_t smem_dst, const void* gsrc) {
    asm volatile("cp.async.cg.shared.global [%0], [%1], 16;"
                 :: "r"(smem_dst), "l"(gsrc));
}
__device__ __forceinline__ uint32_t smem_to_u32(const void* p) {
    uint32_t a;
    asm("{ .reg .u64 t; cvta.to.shared.u64 t, %1; cvt.u32.u64 %0, t; }"
        : "=r"(a) : "l"(p));
    return a;
}

// ================= setup split =================
__global__ void k_zero() {
    int i = blockIdx.x * blockDim.x + threadIdx.x;
    if (i < Nn) g_deg[i] = 0;
}

// embed | weight-split | W1T | centers (off critical path, side stream)
#define EB 12500
#define WC 384
#define T1 64
#define CB 20
__global__ void k_setup_rest(const int* __restrict__ z, const float* __restrict__ zt,
                             const float* __restrict__ Wl, const float* __restrict__ Wr,
                             const float* __restrict__ W1, const int* __restrict__ batch) {
    int b = blockIdx.x, t = threadIdx.x;
    if (b < EB) {
        int i = b * 256 + t;
        int n = i >> 5, q = i & 31;
        int zz = z[n];
        *(float4*)(g_x + n * Dd + q * 4) = *(const float4*)(zt + zz * Dd + q * 4);
    } else if (b < EB + WC) {
        int i = (b - EB) * 256 + t;   // 6*16384 (m, n, k)
        int m = i >> 14;
        int n = (i >> 7) & 127;
        int k = i & 127;
        const float* src = (m & 1) ? (Wr + (m >> 1) * Dd * Dd) : (Wl + (m >> 1) * Dd * Dd);
        float w = src[n * Dd + k];
        uint32_t u = __float_as_uint(w);
        uint32_t hb = (u + 0x7fffu + ((u >> 16) & 1u)) >> 16;
        float hf = __uint_as_float(hb << 16);
        float l = w - hf;
        uint32_t ul = __float_as_uint(l);
        uint32_t lb = (ul + 0x7fffu + ((ul >> 16) & 1u)) >> 16;
        uint32_t off = (uint32_t)(k >> 6) * 16384u
                     + sw128((uint32_t)n * 128u + (uint32_t)(k & 63) * 2u);
        *(unsigned short*)((char*)g_Wbf[m][0] + off) = (unsigned short)hb;
        *(unsigned short*)((char*)g_Wbf[m][1] + off) = (unsigned short)lb;
    } else if (b < EB + WC + T1) {
        int i = (b - EB - WC) * 256 + t;
        int k = i >> 7, j = i & 127;
        g_W1T[i] = W1[j * Dd + k];
    } else {
        int g = (b - EB - WC - T1) * 256 + t;
        if (g < Gg) {
            int lo = 0, hi = Nn;
            while (lo < hi) {
                int mid = (lo + hi) >> 1;
                if (batch[mid] < g) lo = mid + 1; else hi = mid;
            }
            g_centers[g] = lo;
        }
    }
}

// ================= CSR build =================
__global__ void k_deg(const int* __restrict__ dst) {
    int e = blockIdx.x * blockDim.x + threadIdx.x;
    if (e < Ee) atomicAdd(&g_deg[dst[e]], 1);
}
__global__ void k_scan1() {
    __shared__ int sh[SCAN_T];
    int b = blockIdx.x, t = threadIdx.x;
    int i = b * CHUNK + t;
    int v = (t < CHUNK && i < Nn) ? g_deg[i] : 0;
    sh[t] = v;
    __syncthreads();
    for (int off = 1; off < SCAN_T; off <<= 1) {
        int y = (t >= off) ? sh[t - off] : 0;
        __syncthreads();
        sh[t] += y;
        __syncthreads();
    }
    if (t < CHUNK && i < Nn) g_rowoff[i] = sh[t] - v;
    if (t == SCAN_T - 1) g_part[b] = sh[SCAN_T - 1];
}
// merged scan2+scan3: each block recomputes the 256-partial prefix itself
__global__ void k_scan23() {
    __shared__ int sp[SCAN_B];
    int b = blockIdx.x, t = threadIdx.x;
    if (t < SCAN_B) sp[t] = g_part[t];
    __syncthreads();
    for (int off = 1; off < SCAN_B; off <<= 1) {
        int y = (t < SCAN_B && t >= off) ? sp[t - off] : 0;
        __syncthreads();
        if (t < SCAN_B) sp[t] += y;
        __syncthreads();
    }
    int base = (b > 0) ? sp[b - 1] : 0;
    int i = b * CHUNK + t;
    if (t < CHUNK && i < Nn) {
        int v = g_rowoff[i] + base;
        g_rowoff[i] = v;
        g_cursor[i] = v;
        int d = g_deg[i];
        g_invdeg[i] = 1.0f / (float)(d > 0 ? d : 1);
    }
    if (b == 0 && t == 0) g_rowoff[Nn] = Ee;
}
__global__ void k_csr(const int* __restrict__ src, const int* __restrict__ dst) {
    int e = blockIdx.x * blockDim.x + threadIdx.x;
    if (e < Ee) {
        int d = dst[e];
        int pos = atomicAdd(&g_cursor[d], 1);
        g_csr[pos] = src[e];
    }
}

// ================= aggregation: gather + direct bf16 hi/lo image write ==========
__global__ void __launch_bounds__(256) k_agg(int xsel) {
    const float* __restrict__ x = xsel ? g_y : g_x;
    int w = (blockIdx.x * blockDim.x + threadIdx.x) >> 5;
    if (w >= Nn) return;
    int lane = threadIdx.x & 31;
    int beg = g_rowoff[w], end = g_rowoff[w + 1];
    float4 a0 = make_float4(0.f, 0.f, 0.f, 0.f);
    float4 a1 = make_float4(0.f, 0.f, 0.f, 0.f);
    float4 a2 = make_float4(0.f, 0.f, 0.f, 0.f);
    float4 a3 = make_float4(0.f, 0.f, 0.f, 0.f);
    int e = beg;
    for (; e + 4 <= end; e += 4) {
        int s0 = g_csr[e], s1 = g_csr[e + 1], s2 = g_csr[e + 2], s3 = g_csr[e + 3];
        float4 v0 = *(const float4*)(x + s0 * Dd + lane * 4);
        float4 v1 = *(const float4*)(x + s1 * Dd + lane * 4);
        float4 v2 = *(const float4*)(x + s2 * Dd + lane * 4);
        float4 v3 = *(const float4*)(x + s3 * Dd + lane * 4);
        a0.x += v0.x; a0.y += v0.y; a0.z += v0.z; a0.w += v0.w;
        a1.x += v1.x; a1.y += v1.y; a1.z += v1.z; a1.w += v1.w;
        a2.x += v2.x; a2.y += v2.y; a2.z += v2.z; a2.w += v2.w;
        a3.x += v3.x; a3.y += v3.y; a3.z += v3.z; a3.w += v3.w;
    }
    for (; e < end; e++) {
        int s0 = g_csr[e];
        float4 v0 = *(const float4*)(x + s0 * Dd + lane * 4);
        a0.x += v0.x; a0.y += v0.y; a0.z += v0.z; a0.w += v0.w;
    }
    float sc = g_invdeg[w];
    float4 r;
    r.x = (a0.x + a1.x + a2.x + a3.x) * sc;
    r.y = (a0.y + a1.y + a2.y + a3.y) * sc;
    r.z = (a0.z + a1.z + a2.z + a3.z) * sc;
    r.w = (a0.w + a1.w + a2.w + a3.w) * sc;
    uint32_t h0, h1, l0, l1;
    asm("cvt.rn.bf16x2.f32 %0, %1, %2;" : "=r"(h0) : "f"(r.y), "f"(r.x));
    asm("cvt.rn.bf16x2.f32 %0, %1, %2;" : "=r"(h1) : "f"(r.w), "f"(r.z));
    float e0 = r.x - __uint_as_float(h0 << 16);
    float e1 = r.y - __uint_as_float(h0 & 0xffff0000u);
    float e2 = r.z - __uint_as_float(h1 << 16);
    float e3 = r.w - __uint_as_float(h1 & 0xffff0000u);
    asm("cvt.rn.bf16x2.f32 %0, %1, %2;" : "=r"(l0) : "f"(e1), "f"(e0));
    asm("cvt.rn.bf16x2.f32 %0, %1, %2;" : "=r"(l1) : "f"(e3), "f"(e2));
    int tile = w >> 7, rr = w & 127;
    int k0 = lane * 4;
    uint32_t off = sw128((uint32_t)(rr * 128 + (k0 & 63) * 2));
    size_t base = ((size_t)tile * 2 + (size_t)(k0 >> 6)) * 16384 + off;
    *(uint2*)((char*)g_Abf[0] + base) = make_uint2(h0, h1);
    *(uint2*)((char*)g_Abf[1] + base) = make_uint2(l0, l1);
}

// ================= mma.sync bf16-split GEMM =================
#define HG_SMEM 65536
extern __shared__ char s_hg[];

__device__ __forceinline__ void ldmx4(uint32_t addr, uint32_t f[4]) {
    asm volatile("ldmatrix.sync.aligned.m8n8.x4.shared.b16 {%0,%1,%2,%3}, [%4];"
                 : "=r"(f[0]), "=r"(f[1]), "=r"(f[2]), "=r"(f[3]) : "r"(addr));
}
__device__ __forceinline__ void mma16816(float d[4], const uint32_t a[4],
                                         uint32_t b0, uint32_t b1) {
    asm volatile(
        "mma.sync.aligned.m16n8k16.row.col.f32.bf16.bf16.f32 "
        "{%0,%1,%2,%3}, {%4,%5,%6,%7}, {%8,%9}, {%0,%1,%2,%3};"
        : "+f"(d[0]), "+f"(d[1]), "+f"(d[2]), "+f"(d[3])
        : "r"(a[0]), "r"(a[1]), "r"(a[2]), "r"(a[3]), "r"(b0), "r"(b1));
}

__global__ void __launch_bounds__(256, 2) k_hgemm(int s1sel, int m1, int osel,
                                                  const float* __restrict__ bias,
                                                  int relu, int rmw, int aimg) {
    const float* bufs[2] = {g_x, g_y};
    float* obufs[2] = {g_x, g_y};
    const float* __restrict__ S = bufs[s1sel];
    float* __restrict__ O = obufs[osel];

    uint32_t sb = smem_to_u32(s_hg);
    uint32_t sAhi = sb, sAlo = sb + 16384u, sWhi = sb + 32768u, sWlo = sb + 49152u;
    int tid = threadIdx.x, lane = tid & 31, wid = tid >> 5;
    int wm = wid & 3, wn = wid >> 2;
    int rowBase = blockIdx.x * 128;

    float d[2][8][4];
#pragma unroll
    for (int mt = 0; mt < 2; mt++)
#pragma unroll
        for (int i = 0; i < 8; i++)
#pragma unroll
            for (int j = 0; j < 4; j++) d[mt][i][j] = 0.f;

    int fr = (lane & 7) + ((lane >> 3) & 1) * 8;
    int fk = (lane >> 4) * 8;

    for (int kc = 0; kc < 2; kc++) {
        __syncthreads();
        {
            const char* whp = (const char*)g_Wbf[m1][0] + kc * 16384;
            const char* wlp = (const char*)g_Wbf[m1][1] + kc * 16384;
#pragma unroll
            for (int i = tid; i < 1024; i += 256) {
                cp_async16(sWhi + (uint32_t)i * 16u, whp + i * 16);
                cp_async16(sWlo + (uint32_t)i * 16u, wlp + i * 16);
            }
        }
        if (aimg) {
            size_t cbase = ((size_t)blockIdx.x * 2 + (size_t)kc) * 16384;
            const char* ahp = (const char*)g_Abf[0] + cbase;
            const char* alp = (const char*)g_Abf[1] + cbase;
#pragma unroll
            for (int i = tid; i < 1024; i += 256) {
                cp_async16(sAhi + (uint32_t)i * 16u, ahp + i * 16);
                cp_async16(sAlo + (uint32_t)i * 16u, alp + i * 16);
            }
            asm volatile("cp.async.commit_group;" ::: "memory");
        } else {
            asm volatile("cp.async.commit_group;" ::: "memory");
            int row = tid >> 1, half = tid & 1;
            int grow = rowBase + row;
            const float4* p = (const float4*)(S + (size_t)grow * Dd + kc * 64 + half * 32);
            bool valid = grow < Nn;
#pragma unroll
            for (int j = 0; j < 4; j++) {
                float4 v0 = valid ? p[2 * j] : make_float4(0.f, 0.f, 0.f, 0.f);
                float4 v1 = valid ? p[2 * j + 1] : make_float4(0.f, 0.f, 0.f, 0.f);
                uint32_t h0, h1, h2, h3, l0, l1, l2, l3;
                asm("cvt.rn.bf16x2.f32 %0, %1, %2;" : "=r"(h0) : "f"(v0.y), "f"(v0.x));
                asm("cvt.rn.bf16x2.f32 %0, %1, %2;" : "=r"(h1) : "f"(v0.w), "f"(v0.z));
                asm("cvt.rn.bf16x2.f32 %0, %1, %2;" : "=r"(h2) : "f"(v1.y), "f"(v1.x));
                asm("cvt.rn.bf16x2.f32 %0, %1, %2;" : "=r"(h3) : "f"(v1.w), "f"(v1.z));
                float r0x = v0.x - __uint_as_float(h0 << 16);
                float r0y = v0.y - __uint_as_float(h0 & 0xffff0000u);
                float r0z = v0.z - __uint_as_float(h1 << 16);
                float r0w = v0.w - __uint_as_float(h1 & 0xffff0000u);
                float r1x = v1.x - __uint_as_float(h2 << 16);
                float r1y = v1.y - __uint_as_float(h2 & 0xffff0000u);
                float r1z = v1.z - __uint_as_float(h3 << 16);
                float r1w = v1.w - __uint_as_float(h3 & 0xffff0000u);
                asm("cvt.rn.bf16x2.f32 %0, %1, %2;" : "=r"(l0) : "f"(r0y), "f"(r0x));
                asm("cvt.rn.bf16x2.f32 %0, %1, %2;" : "=r"(l1) : "f"(r0w), "f"(r0z));
                asm("cvt.rn.bf16x2.f32 %0, %1, %2;" : "=r"(l2) : "f"(r1y), "f"(r1x));
                asm("cvt.rn.bf16x2.f32 %0, %1, %2;" : "=r"(l3) : "f"(r1w), "f"(r1z));
                uint32_t off = sw128((uint32_t)(row * 128 + (half * 32 + j * 8) * 2));
                *(uint4*)(s_hg + off) = make_uint4(h0, h1, h2, h3);
                *(uint4*)(s_hg + 16384 + off) = make_uint4(l0, l1, l2, l3);
            }
        }
        asm volatile("cp.async.wait_group 0;" ::: "memory");
        __syncthreads();
#pragma unroll
        for (int ks = 0; ks < 4; ks++) {
            uint32_t aHi[2][4], aLo[2][4];
#pragma unroll
            for (int mt = 0; mt < 2; mt++) {
                uint32_t off = sw128((uint32_t)((wm * 32 + mt * 16 + fr) * 128
                                                + (ks * 16 + fk) * 2));
                ldmx4(sAhi + off, aHi[mt]);
                ldmx4(sAlo + off, aLo[mt]);
            }
#pragma unroll
            for (int nc = 0; nc < 4; nc++) {
                uint32_t off = sw128((uint32_t)((wn * 64 + nc * 16 + fr) * 128
                                                + (ks * 16 + fk) * 2));
                uint32_t bH[4], bL[4];
                ldmx4(sWhi + off, bH);
                ldmx4(sWlo + off, bL);
#pragma unroll
                for (int mt = 0; mt < 2; mt++) {
                    mma16816(d[mt][nc * 2 + 0], aHi[mt], bH[0], bH[2]);
                    mma16816(d[mt][nc * 2 + 1], aHi[mt], bH[1], bH[3]);
                    mma16816(d[mt][nc * 2 + 0], aHi[mt], bL[0], bL[2]);
                    mma16816(d[mt][nc * 2 + 1], aHi[mt], bL[1], bL[3]);
                    mma16816(d[mt][nc * 2 + 0], aLo[mt], bH[0], bH[2]);
                    mma16816(d[mt][nc * 2 + 1], aLo[mt], bH[1], bH[3]);
                }
            }
        }
    }

    // ---- epilogue ----
#pragma unroll
    for (int mt = 0; mt < 2; mt++) {
        int row0 = rowBase + wm * 32 + mt * 16 + (lane >> 2);
#pragma unroll
        for (int i = 0; i < 8; i++) {
            int col = wn * 64 + i * 8 + (lane & 3) * 2;
            float2 bv = bias ? *(const float2*)(bias + col) : make_float2(0.f, 0.f);
#pragma unroll
            for (int h = 0; h < 2; h++) {
                int row = row0 + h * 8;
                if (row < Nn) {
                    float2 o;
                    o.x = d[mt][i][2 * h + 0] + bv.x;
                    o.y = d[mt][i][2 * h + 1] + bv.y;
                    float* op = O + (size_t)row * Dd + col;
                    if (rmw) {
                        float2 pv = *(const float2*)op;
                        o.x += pv.x; o.y += pv.y;
                    }
                    if (relu) {
                        o.x = fmaxf(o.x, 0.f);
                        o.y = fmaxf(o.y, 0.f);
                    }
                    *(float2*)op = o;
                }
            }
        }
    }
}

// ================= readout =================
__global__ void __launch_bounds__(128) k_readout(const float* __restrict__ b1,
                                                 const float* __restrict__ W2,
                                                 const float* __restrict__ b2,
                                                 float* __restrict__ out) {
    __shared__ float h[128];
    __shared__ float red[4];
    int g = blockIdx.x, j = threadIdx.x;
    int c = g_centers[g];
    h[j] = g_y[c * Dd + j] * g_y[(c + 1) * Dd + j];
    __syncthreads();
    float t = b1[j];
    const float* __restrict__ w1t = g_W1T + j;
#pragma unroll 8
    for (int k = 0; k < 128; k++) t += h[k] * w1t[k * 128];
    t = fmaxf(t, 0.f) * W2[j];
    for (int off = 16; off; off >>= 1) t += __shfl_down_sync(0xffffffffu, t, off);
    if ((j & 31) == 0) red[j >> 5] = t;
    __syncthreads();
    if (j == 0) out[g] = red[0] + red[1] + red[2] + red[3] + b2[0];
}

// ================= launch: overlapped head, capture-legal fork =================
extern "C" void kernel_launch(void* const* d_in, const int* in_sizes, int n_in,
                              void* d_out, int out_size) {
    const int*   z     = (const int*)d_in[0];
    const int*   ei    = (const int*)d_in[1];
    const int*   batch = (const int*)d_in[2];
    const float* zt    = (const float*)d_in[3];
    const float* Wl    = (const float*)d_in[4];
    const float* bl    = (const float*)d_in[5];
    const float* Wr    = (const float*)d_in[6];
    const float* W1    = (const float*)d_in[7];
    const float* b1    = (const float*)d_in[8];
    const float* W2    = (const float*)d_in[9];
    const float* b2    = (const float*)d_in[10];
    float* out = (float*)d_out;

    const int* esrc = ei;
    const int* edst = ei + Ee;

    static cudaStream_t sB = nullptr;
    static cudaEvent_t ev0, evS, evF[Ll], evJ[Ll];
    if (!sB) {
        cudaStreamCreateWithFlags(&sB, cudaStreamNonBlocking);
        cudaEventCreateWithFlags(&ev0, cudaEventDisableTiming);
        cudaEventCreateWithFlags(&evS, cudaEventDisableTiming);
        for (int i = 0; i < Ll; i++) {
            cudaEventCreateWithFlags(&evF[i], cudaEventDisableTiming);
            cudaEventCreateWithFlags(&evJ[i], cudaEventDisableTiming);
        }
    }
    cudaStream_t s0 = (cudaStream_t)0;

    cudaFuncSetAttribute(k_hgemm, cudaFuncAttributeMaxDynamicSharedMemorySize, HG_SMEM);

    int aggGrid = (Nn * 32 + 255) / 256;
    int eGrid = (Ee + 255) / 256;

    // capture-legal fork: sB's FIRST op is a wait on an event recorded on s0
    k_zero<<<(Nn + 255) / 256, 256, 0, s0>>>();                                   // #1
    cudaEventRecord(ev0, s0);                                                     // fork point
    cudaStreamWaitEvent(sB, ev0, 0);                                              // sB joins capture
    k_setup_rest<<<EB + WC + T1 + CB, 256, 0, sB>>>(z, zt, Wl, Wr, W1, batch);    // #2 (side)
    k_deg<<<eGrid, 256, 0, s0>>>(edst);                                           // #3
    k_hgemm<<<GB, 256, HG_SMEM, sB>>>(0, 1, 1, nullptr, 0, 0, 0);                 // #4 <- profiled (side)
    cudaEventRecord(evS, sB);           // embed + Wr0 done marker
    k_scan1<<<SCAN_B, SCAN_T, 0, s0>>>();                                         // #5
    k_scan23<<<SCAN_B, SCAN_T, 0, s0>>>();                                        // #6
    k_csr<<<eGrid, 256, 0, s0>>>(esrc, edst);                                     // #7
    cudaStreamWaitEvent(s0, evS, 0);    // embed done before gather reads g_x
    k_agg<<<aggGrid, 256, 0, s0>>>(0);                                            // #8
    k_hgemm<<<GB, 256, HG_SMEM, s0>>>(0, 0, 1, bl, 1, 1, 1);                      // #9: g_y += img@Wl0 +b, relu

    for (int l = 1; l < Ll; l++) {
        int xs = (l == 1) ? 1 : 0;
        int os = (l == 1) ? 0 : 1;
        cudaEventRecord(evF[l], s0);
        cudaStreamWaitEvent(sB, evF[l], 0);
        k_hgemm<<<GB, 256, HG_SMEM, sB>>>(xs, 2 * l + 1, os, nullptr, 0, 0, 0);   // Wr (convert mode, hidden)
        k_agg<<<aggGrid, 256, 0, s0>>>(xs);                                       // agg -> bf16 images
        cudaEventRecord(evJ[l], sB);
        cudaStreamWaitEvent(s0, evJ[l], 0);
        k_hgemm<<<GB, 256, HG_SMEM, s0>>>(0, 2 * l, os, bl + l * Dd,
                                          (l < Ll - 1) ? 1 : 0, 1, 1);            // Wl (image mode)
    }

    k_readout<<<Gg, 128, 0, s0>>>(b1, W2, b2, out);
}